// round 4
// baseline (speedup 1.0000x reference)
#include <cuda_runtime.h>
#include <cstdint>

#define NPTS 50000
#define DIM  128
#define W4   (DIM / 4)
#define TANCH 1024
#define KNEG 10
#define MH 16                 // per-window candidate margin
#define NWIN 8                // windows per segment
#define GAMMA 1.0f
#define QSCALE 20.0f

#define MA 16                 // anchors per CTA
#define TN 256                // candidates per tile
#define CW 8                  // words per chunk (32 dims)
#define NCH (W4 / CW)
#define STAGES 3
#define SSEG 4
#define TILES_PER_SEG 50
#define SEG_LEN (TILES_PER_SEG * TN)    // 12800
#define N_PAD (SSEG * SEG_LEN)          // 51200
#define TOTCH (TILES_PER_SEG * NCH)     // 200

// ---------------- static scratch ----------------
__device__ uint32_t g_BTq[2][W4][N_PAD];    // packed s8x4, transposed; pad word = 0
__device__ int g_sumb2[2][N_PAD];           // per-point sum of squares (pad = big)
__device__ int g_candi[2][TANCH][SSEG][NWIN][MH];
__device__ float g_partial[2 * TANCH];

// ---------------- helpers ----------------
__device__ __forceinline__ int dp4a(int acc, uint32_t a, uint32_t b) {
    int r;
    asm("dp4a.s32.s32 %0, %1, %2, %3;" : "=r"(r) : "r"(a), "r"(b), "r"(acc));
    return r;
}
__device__ __forceinline__ int quants(float v) {
    return min(127, max(-127, __float2int_rn(v * QSCALE)));
}
__device__ __forceinline__ uint32_t pack4(int q0, int q1, int q2, int q3) {
    return (uint32_t)(q0 & 0xFF) | ((uint32_t)(q1 & 0xFF) << 8) |
           ((uint32_t)(q2 & 0xFF) << 16) | ((uint32_t)(q3 & 0xFF) << 24);
}
__device__ __forceinline__ void cp_async16(uint32_t s, const void* g) {
    asm volatile("cp.async.cg.shared.global [%0], [%1], 16;\n" :: "r"(s), "l"(g));
}
__device__ __forceinline__ void cp_commit() { asm volatile("cp.async.commit_group;\n"); }
template <int N> __device__ __forceinline__ void cp_wait() {
    asm volatile("cp.async.wait_group %0;\n" :: "n"(N));
}
__device__ __forceinline__ float warp_sum(float v) {
    #pragma unroll
    for (int o = 16; o > 0; o >>= 1) v += __shfl_xor_sync(0xffffffffu, v, o);
    return v;
}

// ---------------- kernel 1: quantize(s8) + pack + transpose + sumsq ----------------
__global__ void quant_transpose_kernel(const float* __restrict__ out1,
                                       const float* __restrict__ out2) {
    __shared__ uint32_t tile[32][33];
    const float* src = (blockIdx.z == 0) ? out1 : out2;
    uint32_t* dst = &g_BTq[blockIdx.z][0][0];
    const int nBase = blockIdx.x * 32;
    const int tx = threadIdx.x, ty = threadIdx.y;
    #pragma unroll
    for (int j = 0; j < 32; j += 8) {
        int n = nBase + ty + j;
        uint32_t w = 0;
        int sq = 0x01000000;                 // pad: total = 0x20000000 per point
        if (n < NPTS) {
            float4 v = *(const float4*)(src + n * DIM + 4 * tx);
            int q0 = quants(v.x), q1 = quants(v.y), q2 = quants(v.z), q3 = quants(v.w);
            w = pack4(q0, q1, q2, q3);
            sq = q0 * q0 + q1 * q1 + q2 * q2 + q3 * q3;
        }
        tile[ty + j][tx] = w;
        int tot = sq;
        #pragma unroll
        for (int o = 16; o > 0; o >>= 1) tot += __shfl_xor_sync(0xffffffffu, tot, o);
        if (tx == 0) g_sumb2[blockIdx.z][n] = tot;
    }
    __syncthreads();
    #pragma unroll
    for (int j = 0; j < 32; j += 8) {
        int d4 = ty + j;
        dst[d4 * N_PAD + nBase + tx] = tile[tx][d4];
    }
}

// ---------------- kernel 2: dp4a L2-key mining ----------------
__global__ __launch_bounds__(256, 4)
void mine_kernel(const float* __restrict__ out1, const float* __restrict__ out2,
                 const int* __restrict__ anchor1, const int* __restrict__ anchor2) {
    __shared__ uint32_t Aq[W4][MA];
    __shared__ uint32_t Bq[STAGES][CW][TN];
    __shared__ int s_kd[MA][MH];
    __shared__ int s_ki[MA][MH];

    const int dir = blockIdx.z;
    const int bsel = (dir == 0) ? 1 : 0;
    const int tBase = blockIdx.x * MA;
    const int seg = blockIdx.y;
    const float* Arows = (dir == 0) ? out1 : out2;
    const int*   anch  = (dir == 0) ? anchor1 : anchor2;
    const uint32_t* BTq = &g_BTq[bsel][0][0];

    const int t = threadIdx.x;
    const int lane = t & 31;
    const int aB = (t >> 5) * 2;
    const int cB = lane * 8;
    const int segStart = seg * SEG_LEN;

    // quantize 16 anchor rows (identical quantizer to kernel 1)
    #pragma unroll
    for (int i = 0; i < 2; ++i) {
        int id = t + 256 * i;
        int a = id >> 5, w = id & 31;
        float4 v = *(const float4*)(Arows + anch[tBase + a] * DIM + 4 * w);
        Aq[w][a] = pack4(quants(v.x), quants(v.y), quants(v.z), quants(v.w));
    }
    if (t < MA) {
        #pragma unroll
        for (int k = 0; k < MH; ++k) { s_kd[t][k] = 0x7fffffff; s_ki[t][k] = 0; }
    }
    __syncthreads();

    auto load_chunk = [&](int s, int g) {
        uint32_t sb = (uint32_t)__cvta_generic_to_shared(&Bq[s][0][0]);
        const int n0 = segStart + (g >> 2) * TN;
        const int rowBase = (g & 3) * CW;
        #pragma unroll
        for (int i = 0; i < 2; ++i) {
            int id = t + 256 * i;
            int r = id >> 6;
            int c4 = (id & 63) * 4;
            const uint32_t* gp = BTq + (rowBase + r) * N_PAD + n0 + c4;
            cp_async16(sb + (uint32_t)((r * TN + c4) * 4), gp);
        }
        cp_commit();
    };

    load_chunk(0, 0);
    load_chunk(1, 1);

    int worst0 = 0x7fffffff, worst1 = 0x7fffffff;   // valid in lane 0
    int wi = 0;
    int nextB = (TILES_PER_SEG * 1 + NWIN - 1) / NWIN;   // 7

    for (int tile = 0; tile < TILES_PER_SEG; ++tile) {
        int acc0[8], acc1[8];
        #pragma unroll
        for (int j = 0; j < 8; ++j) { acc0[j] = 0; acc1[j] = 0; }

        #pragma unroll
        for (int c = 0; c < NCH; ++c) {
            const int g = tile * NCH + c;
            if (g + 1 < TOTCH) cp_wait<1>(); else cp_wait<0>();
            __syncthreads();
            if (g + 2 < TOTCH) load_chunk((g + 2) % STAGES, g + 2);

            const uint32_t* B = &Bq[g % STAGES][0][0];
            const int wg = c * CW;
            #pragma unroll
            for (int w = 0; w < CW; ++w) {
                uint2 aw = *(const uint2*)&Aq[wg + w][aB];
                uint4 b0 = *(const uint4*)&B[w * TN + cB];
                uint4 b1 = *(const uint4*)&B[w * TN + cB + 4];
                acc0[0] = dp4a(acc0[0], aw.x, b0.x);
                acc0[1] = dp4a(acc0[1], aw.x, b0.y);
                acc0[2] = dp4a(acc0[2], aw.x, b0.z);
                acc0[3] = dp4a(acc0[3], aw.x, b0.w);
                acc0[4] = dp4a(acc0[4], aw.x, b1.x);
                acc0[5] = dp4a(acc0[5], aw.x, b1.y);
                acc0[6] = dp4a(acc0[6], aw.x, b1.z);
                acc0[7] = dp4a(acc0[7], aw.x, b1.w);
                acc1[0] = dp4a(acc1[0], aw.y, b0.x);
                acc1[1] = dp4a(acc1[1], aw.y, b0.y);
                acc1[2] = dp4a(acc1[2], aw.y, b0.z);
                acc1[3] = dp4a(acc1[3], aw.y, b0.w);
                acc1[4] = dp4a(acc1[4], aw.y, b1.x);
                acc1[5] = dp4a(acc1[5], aw.y, b1.y);
                acc1[6] = dp4a(acc1[6], aw.y, b1.z);
                acc1[7] = dp4a(acc1[7], aw.y, b1.w);
            }
        }

        // keys: Σb² - 2·dot   (in-place over accumulators)
        const int n0 = segStart + tile * TN;
        {
            const int* s2p = &g_sumb2[bsel][n0 + cB];
            int4 sa = *(const int4*)s2p;
            int4 sb = *(const int4*)(s2p + 4);
            acc0[0] = sa.x - 2 * acc0[0];  acc0[1] = sa.y - 2 * acc0[1];
            acc0[2] = sa.z - 2 * acc0[2];  acc0[3] = sa.w - 2 * acc0[3];
            acc0[4] = sb.x - 2 * acc0[4];  acc0[5] = sb.y - 2 * acc0[5];
            acc0[6] = sb.z - 2 * acc0[6];  acc0[7] = sb.w - 2 * acc0[7];
            acc1[0] = sa.x - 2 * acc1[0];  acc1[1] = sa.y - 2 * acc1[1];
            acc1[2] = sa.z - 2 * acc1[2];  acc1[3] = sa.w - 2 * acc1[3];
            acc1[4] = sb.x - 2 * acc1[4];  acc1[5] = sb.y - 2 * acc1[5];
            acc1[6] = sb.z - 2 * acc1[6];  acc1[7] = sb.w - 2 * acc1[7];
        }

        int w0v = __shfl_sync(0xffffffffu, worst0, 0);
        int w1v = __shfl_sync(0xffffffffu, worst1, 0);
        #pragma unroll
        for (int j = 0; j < 8; ++j) {
            unsigned m0 = __ballot_sync(0xffffffffu, acc0[j] < w0v);
            while (m0) {
                int src = __ffs(m0) - 1; m0 &= m0 - 1;
                int d = __shfl_sync(0xffffffffu, acc0[j], src);
                if (lane == 0 && d < worst0) {
                    int idx = n0 + src * 8 + j;
                    int pos = MH - 1;
                    #pragma unroll
                    for (int q = MH - 2; q >= 0; --q)
                        if (s_kd[aB][q] > d) pos = q;
                    for (int q = MH - 1; q > pos; --q) {
                        s_kd[aB][q] = s_kd[aB][q - 1];
                        s_ki[aB][q] = s_ki[aB][q - 1];
                    }
                    s_kd[aB][pos] = d; s_ki[aB][pos] = idx;
                    worst0 = s_kd[aB][MH - 1];
                }
            }
            unsigned m1 = __ballot_sync(0xffffffffu, acc1[j] < w1v);
            while (m1) {
                int src = __ffs(m1) - 1; m1 &= m1 - 1;
                int d = __shfl_sync(0xffffffffu, acc1[j], src);
                if (lane == 0 && d < worst1) {
                    int idx = n0 + src * 8 + j;
                    int pos = MH - 1;
                    #pragma unroll
                    for (int q = MH - 2; q >= 0; --q)
                        if (s_kd[aB + 1][q] > d) pos = q;
                    for (int q = MH - 1; q > pos; --q) {
                        s_kd[aB + 1][q] = s_kd[aB + 1][q - 1];
                        s_ki[aB + 1][q] = s_ki[aB + 1][q - 1];
                    }
                    s_kd[aB + 1][pos] = d; s_ki[aB + 1][pos] = idx;
                    worst1 = s_kd[aB + 1][MH - 1];
                }
            }
        }

        // window flush
        if (tile + 1 == nextB) {
            if (lane == 0) {
                int tg0 = tBase + aB;
                #pragma unroll
                for (int k = 0; k < MH; ++k) {
                    g_candi[dir][tg0][seg][wi][k]     = s_ki[aB][k];
                    g_candi[dir][tg0 + 1][seg][wi][k] = s_ki[aB + 1][k];
                    s_kd[aB][k] = 0x7fffffff;     s_ki[aB][k] = 0;
                    s_kd[aB + 1][k] = 0x7fffffff; s_ki[aB + 1][k] = 0;
                }
                worst0 = 0x7fffffff; worst1 = 0x7fffffff;
            }
            wi++;
            nextB = (TILES_PER_SEG * (wi + 1) + NWIN - 1) / NWIN;
        }
    }
}

// ---------------- kernel 3: exact fp32 L1 re-rank over 512 candidates + loss ----------------
__global__ void refine_loss_kernel(const float* __restrict__ out1, const float* __restrict__ out2,
                                   const int* __restrict__ anchor1, const int* __restrict__ anchor2) {
    const int g = blockIdx.x * 8 + (threadIdx.x >> 5);
    const int lane = threadIdx.x & 31;
    const int dir = g >> 10;
    const int tt = g & 1023;

    const float* r1 = out1 + anchor1[tt] * DIM;
    const float* r2 = out2 + anchor2[tt] * DIM;
    float v1[4], v2[4];
    #pragma unroll
    for (int j = 0; j < 4; ++j) {
        v1[j] = r1[lane + 32 * j];
        v2[j] = r2[lane + 32 * j];
    }
    float A = 0.0f;
    #pragma unroll
    for (int j = 0; j < 4; ++j) A += fabsf(v1[j] - v2[j]);
    A = warp_sum(A);
    const float Dm = A + GAMMA;

    float selfv[4];
    #pragma unroll
    for (int j = 0; j < 4; ++j) selfv[j] = (dir == 0) ? v1[j] : v2[j];
    const float* G = (dir == 0) ? out2 : out1;

    float kd[KNEG]; int ki[KNEG];
    #pragma unroll
    for (int k = 0; k < KNEG; ++k) { kd[k] = 3.0e38f; ki[k] = 0x7fffffff; }

    const int* cand = &g_candi[dir][tt][0][0][0];
    for (int k = 0; k < SSEG * NWIN * MH; ++k) {
        int idx = cand[k];
        idx = min(idx, NPTS - 1);
        const float* nr = G + idx * DIM;
        float dsum = 0.0f;
        #pragma unroll
        for (int j = 0; j < 4; ++j) dsum += fabsf(selfv[j] - nr[lane + 32 * j]);
        dsum = warp_sum(dsum);
        if (lane == 0) {
            bool better = (dsum < kd[KNEG - 1]) ||
                          (dsum == kd[KNEG - 1] && idx < ki[KNEG - 1]);
            if (better) {
                int pos = KNEG - 1;
                for (int q = KNEG - 2; q >= 0; --q)
                    if (kd[q] > dsum || (kd[q] == dsum && ki[q] > idx)) pos = q;
                for (int q = KNEG - 1; q > pos; --q) { kd[q] = kd[q - 1]; ki[q] = ki[q - 1]; }
                kd[pos] = dsum; ki[pos] = idx;
            }
        }
    }
    if (lane == 0) {
        float lsum = 0.0f;
        #pragma unroll
        for (int k = 0; k < KNEG; ++k) lsum += fmaxf(Dm - kd[k], 0.0f);
        g_partial[g] = lsum;
    }
}

// ---------------- kernel 4: deterministic reduction ----------------
__global__ void reduce_kernel(float* __restrict__ out) {
    __shared__ float sh[1024];
    int t = threadIdx.x;
    sh[t] = g_partial[t] + g_partial[t + 1024];
    __syncthreads();
    #pragma unroll
    for (int s = 512; s > 0; s >>= 1) {
        if (t < s) sh[t] += sh[t + s];
        __syncthreads();
    }
    if (t == 0) out[0] = sh[0] * (1.0f / (float)(TANCH * KNEG));
}

// ---------------- launch ----------------
extern "C" void kernel_launch(void* const* d_in, const int* in_sizes, int n_in,
                              void* d_out, int out_size) {
    const float* out1 = (const float*)d_in[0];
    const float* out2 = (const float*)d_in[1];
    const int* anchor1 = (const int*)d_in[2];
    const int* anchor2 = (const int*)d_in[3];
    float* out = (float*)d_out;

    quant_transpose_kernel<<<dim3(N_PAD / 32, 1, 2), dim3(32, 8)>>>(out1, out2);

    mine_kernel<<<dim3(TANCH / MA, SSEG, 2), 256>>>(out1, out2, anchor1, anchor2);

    refine_loss_kernel<<<2 * TANCH / 8, 256>>>(out1, out2, anchor1, anchor2);

    reduce_kernel<<<1, 1024>>>(out);
}

// round 6
// speedup vs baseline: 2.2542x; 2.2542x over previous
#include <cuda_runtime.h>
#include <cstdint>

#define NPTS 50000
#define DIM  128
#define W4   (DIM / 4)
#define TANCH 1024
#define KNEG 10
#define GAMMA 1.0f
#define QSCALE 20.0f

#define MA 32                 // anchors per CTA (4 per warp)
#define TN 256                // candidates per tile
#define CW 8                  // words per chunk (32 dims)
#define NCH (W4 / CW)         // 4
#define STAGES 3
#define SSEG 4
#define TILES_PER_SEG 50
#define SEG_LEN (TILES_PER_SEG * TN)    // 12800
#define N_PAD (SSEG * SEG_LEN)          // 51200
#define TOTCH (TILES_PER_SEG * NCH)     // 200

#define NSAMP 2048            // tau sample size
#define KTAU 24               // tau = 24th smallest sample key -> pool ~585
#define PCAP 320              // pool capacity per (anchor, segment)

// ---------------- static scratch ----------------
__device__ uint32_t g_BTq[2][W4][N_PAD];    // packed s8x4, transposed; pad word = 0
__device__ uint32_t g_Qrow[2][NPTS][W4];    // packed s8x4, row-major (for tau sampling)
__device__ int g_sumb2[2][N_PAD];           // per-point sum of squares (pad = huge)
__device__ int g_tau[2][TANCH];
__device__ int g_pool[2][TANCH][SSEG][PCAP];
__device__ int g_cnt[2][TANCH][SSEG];
__device__ float g_partial[2 * TANCH];

// ---------------- helpers ----------------
__device__ __forceinline__ int dp4a(int acc, uint32_t a, uint32_t b) {
    int r;
    asm("dp4a.s32.s32 %0, %1, %2, %3;" : "=r"(r) : "r"(a), "r"(b), "r"(acc));
    return r;
}
__device__ __forceinline__ int quants(float v) {
    return min(127, max(-127, __float2int_rn(v * QSCALE)));
}
__device__ __forceinline__ uint32_t pack4(int q0, int q1, int q2, int q3) {
    return (uint32_t)(q0 & 0xFF) | ((uint32_t)(q1 & 0xFF) << 8) |
           ((uint32_t)(q2 & 0xFF) << 16) | ((uint32_t)(q3 & 0xFF) << 24);
}
__device__ __forceinline__ void cp_async16(uint32_t s, const void* g) {
    asm volatile("cp.async.cg.shared.global [%0], [%1], 16;\n" :: "r"(s), "l"(g));
}
__device__ __forceinline__ void cp_commit() { asm volatile("cp.async.commit_group;\n"); }
template <int N> __device__ __forceinline__ void cp_wait() {
    asm volatile("cp.async.wait_group %0;\n" :: "n"(N));
}
__device__ __forceinline__ float warp_sum(float v) {
    #pragma unroll
    for (int o = 16; o > 0; o >>= 1) v += __shfl_xor_sync(0xffffffffu, v, o);
    return v;
}
__device__ __forceinline__ int warp_min(int v) {
    #pragma unroll
    for (int o = 16; o > 0; o >>= 1) v = min(v, __shfl_xor_sync(0xffffffffu, v, o));
    return v;
}

// ---------------- kernel 1: quantize + pack + transpose + row copy + sumsq ----------------
__global__ void quant_transpose_kernel(const float* __restrict__ out1,
                                       const float* __restrict__ out2) {
    __shared__ uint32_t tile[32][33];
    const float* src = (blockIdx.z == 0) ? out1 : out2;
    uint32_t* dstT = &g_BTq[blockIdx.z][0][0];
    uint32_t* dstR = &g_Qrow[blockIdx.z][0][0];
    const int nBase = blockIdx.x * 32;
    const int tx = threadIdx.x, ty = threadIdx.y;
    #pragma unroll
    for (int j = 0; j < 32; j += 8) {
        int n = nBase + ty + j;
        uint32_t w = 0;
        int sq = 0x01000000;                 // pad: total = 0x20000000
        if (n < NPTS) {
            float4 v = *(const float4*)(src + n * DIM + 4 * tx);
            int q0 = quants(v.x), q1 = quants(v.y), q2 = quants(v.z), q3 = quants(v.w);
            w = pack4(q0, q1, q2, q3);
            sq = q0 * q0 + q1 * q1 + q2 * q2 + q3 * q3;
            dstR[n * W4 + tx] = w;
        }
        tile[ty + j][tx] = w;
        int tot = sq;
        #pragma unroll
        for (int o = 16; o > 0; o >>= 1) tot += __shfl_xor_sync(0xffffffffu, tot, o);
        if (tx == 0) g_sumb2[blockIdx.z][n] = tot;
    }
    __syncthreads();
    #pragma unroll
    for (int j = 0; j < 32; j += 8) {
        int d4 = ty + j;
        dstT[d4 * N_PAD + nBase + tx] = tile[tx][d4];
    }
}

// ---------------- kernel 2: tau threshold (24th smallest sample key) ----------------
__global__ __launch_bounds__(256)
void tau_kernel(const float* __restrict__ out1, const float* __restrict__ out2,
                const int* __restrict__ anchor1, const int* __restrict__ anchor2) {
    __shared__ uint32_t A_s[8][W4];
    const int warpId = threadIdx.x >> 5;
    const int lane = threadIdx.x & 31;
    const int g = blockIdx.x * 8 + warpId;
    const int dir = g >> 10;
    const int tt = g & 1023;
    const int bsel = (dir == 0) ? 1 : 0;
    const float* Arows = (dir == 0) ? out1 : out2;
    const int* anch = (dir == 0) ? anchor1 : anchor2;

    {
        float4 v = *(const float4*)(Arows + anch[tt] * DIM + 4 * lane);
        A_s[warpId][lane] = pack4(quants(v.x), quants(v.y), quants(v.z), quants(v.w));
    }
    __syncwarp();

    int kd[KTAU];
    #pragma unroll
    for (int k = 0; k < KTAU; ++k) kd[k] = 0x7fffffff;

    const uint32_t* A = A_s[warpId];
    for (int i = 0; i < NSAMP / 32; ++i) {
        int n = i * 32 + lane;
        const uint4* rp = (const uint4*)&g_Qrow[bsel][n][0];
        int dot = 0;
        #pragma unroll
        for (int w8 = 0; w8 < 8; ++w8) {
            uint4 b = rp[w8];
            uint4 a = *(const uint4*)&A[w8 * 4];
            dot = dp4a(dot, a.x, b.x);
            dot = dp4a(dot, a.y, b.y);
            dot = dp4a(dot, a.z, b.z);
            dot = dp4a(dot, a.w, b.w);
        }
        int key = g_sumb2[bsel][n] - 2 * dot;
        if (key < kd[KTAU - 1]) {
            #pragma unroll
            for (int j = KTAU - 1; j > 0; --j)
                kd[j] = min(kd[j], max(kd[j - 1], key));
            kd[0] = min(kd[0], key);
        }
    }

    // extract 24th smallest across warp
    int tauv = 0x7fffffff;
    #pragma unroll
    for (int r = 0; r < KTAU; ++r) {
        int gm = warp_min(kd[0]);
        if (kd[0] == gm) {
            #pragma unroll
            for (int j = 0; j < KTAU - 1; ++j) kd[j] = kd[j + 1];
            kd[KTAU - 1] = 0x7fffffff;
        }
        tauv = gm;
    }
    if (lane == 0) g_tau[dir][tt] = tauv;
}

// ---------------- kernel 3: dp4a mining with seeded threshold, pool append ----------------
__global__ __launch_bounds__(256, 3)
void mine_kernel(const float* __restrict__ out1, const float* __restrict__ out2,
                 const int* __restrict__ anchor1, const int* __restrict__ anchor2) {
    __shared__ uint32_t Aq[W4][MA];            // 4 KB
    __shared__ uint32_t Bq[STAGES][CW][TN];    // 24 KB
    __shared__ int tau_s[MA];

    const int dir = blockIdx.z;
    const int bsel = (dir == 0) ? 1 : 0;
    const int tBase = blockIdx.x * MA;
    const int seg = blockIdx.y;
    const float* Arows = (dir == 0) ? out1 : out2;
    const int*   anch  = (dir == 0) ? anchor1 : anchor2;
    const uint32_t* BTq = &g_BTq[bsel][0][0];

    const int t = threadIdx.x;
    const int lane = t & 31;
    const int warpId = t >> 5;
    const int aB = warpId * 4;
    const int cB = lane * 8;
    const int segStart = seg * SEG_LEN;

    // quantize 32 anchor rows into Aq[word][anchor]
    #pragma unroll
    for (int i = 0; i < 4; ++i) {
        int id = t + 256 * i;          // id = a*32 + w
        int a = id >> 5, w = id & 31;
        float4 v = *(const float4*)(Arows + anch[tBase + a] * DIM + 4 * w);
        Aq[w][a] = pack4(quants(v.x), quants(v.y), quants(v.z), quants(v.w));
    }
    if (t < MA) tau_s[t] = g_tau[dir][tBase + t];
    __syncthreads();

    int taus[4];
    #pragma unroll
    for (int a = 0; a < 4; ++a) taus[a] = tau_s[aB + a];
    int cnt[4] = {0, 0, 0, 0};

    auto load_chunk = [&](int s, int g) {
        uint32_t sb = (uint32_t)__cvta_generic_to_shared(&Bq[s][0][0]);
        const int n0 = segStart + (g >> 2) * TN;
        const int rowBase = (g & 3) * CW;
        #pragma unroll
        for (int i = 0; i < 2; ++i) {
            int id = t + 256 * i;              // 512 x 16B
            int r = id >> 6;
            int c4 = (id & 63) * 4;
            const uint32_t* gp = BTq + (rowBase + r) * N_PAD + n0 + c4;
            cp_async16(sb + (uint32_t)((r * TN + c4) * 4), gp);
        }
        cp_commit();
    };

    load_chunk(0, 0);
    load_chunk(1, 1);

    for (int tile = 0; tile < TILES_PER_SEG; ++tile) {
        int acc[4][8];
        #pragma unroll
        for (int a = 0; a < 4; ++a)
            #pragma unroll
            for (int j = 0; j < 8; ++j) acc[a][j] = 0;

        #pragma unroll
        for (int c = 0; c < NCH; ++c) {
            const int g = tile * NCH + c;
            if (g + 1 < TOTCH) cp_wait<1>(); else cp_wait<0>();
            __syncthreads();
            if (g + 2 < TOTCH) load_chunk((g + 2) % STAGES, g + 2);

            const uint32_t* B = &Bq[g % STAGES][0][0];
            #pragma unroll
            for (int w = 0; w < CW; ++w) {
                uint4 av = *(const uint4*)&Aq[c * CW + w][aB];
                uint4 b0 = *(const uint4*)&B[w * TN + cB];
                uint4 b1 = *(const uint4*)&B[w * TN + cB + 4];
                const uint32_t avr[4] = {av.x, av.y, av.z, av.w};
                const uint32_t bw[8] = {b0.x, b0.y, b0.z, b0.w, b1.x, b1.y, b1.z, b1.w};
                #pragma unroll
                for (int a = 0; a < 4; ++a)
                    #pragma unroll
                    for (int j = 0; j < 8; ++j)
                        acc[a][j] = dp4a(acc[a][j], avr[a], bw[j]);
            }
        }

        // finalize keys + threshold append
        const int n0 = segStart + tile * TN;
        int4 sa = *(const int4*)&g_sumb2[bsel][n0 + cB];
        int4 sb = *(const int4*)&g_sumb2[bsel][n0 + cB + 4];
        const int s2[8] = {sa.x, sa.y, sa.z, sa.w, sb.x, sb.y, sb.z, sb.w};
        #pragma unroll
        for (int a = 0; a < 4; ++a) {
            #pragma unroll
            for (int j = 0; j < 8; ++j) {
                int key = s2[j] - 2 * acc[a][j];
                unsigned m = __ballot_sync(0xffffffffu, key < taus[a]);
                while (m) {
                    int src = __ffs(m) - 1; m &= m - 1;
                    if (cnt[a] < PCAP && lane == 0)
                        g_pool[dir][tBase + aB + a][seg][cnt[a]] = n0 + src * 8 + j;
                    cnt[a]++;
                }
            }
        }
    }

    if (lane == 0) {
        #pragma unroll
        for (int a = 0; a < 4; ++a)
            g_cnt[dir][tBase + aB + a][seg] = min(cnt[a], PCAP);
    }
}

// ---------------- kernel 4: exact fp32 L1 re-rank over pool + loss ----------------
__global__ void refine_loss_kernel(const float* __restrict__ out1, const float* __restrict__ out2,
                                   const int* __restrict__ anchor1, const int* __restrict__ anchor2) {
    const int g = blockIdx.x * 8 + (threadIdx.x >> 5);
    const int lane = threadIdx.x & 31;
    const int dir = g >> 10;
    const int tt = g & 1023;

    const float* r1 = out1 + anchor1[tt] * DIM;
    const float* r2 = out2 + anchor2[tt] * DIM;
    float v1[4], v2[4];
    #pragma unroll
    for (int j = 0; j < 4; ++j) {
        v1[j] = r1[lane + 32 * j];
        v2[j] = r2[lane + 32 * j];
    }
    float A = 0.0f;
    #pragma unroll
    for (int j = 0; j < 4; ++j) A += fabsf(v1[j] - v2[j]);
    A = warp_sum(A);
    const float Dm = A + GAMMA;

    float selfv[4];
    #pragma unroll
    for (int j = 0; j < 4; ++j) selfv[j] = (dir == 0) ? v1[j] : v2[j];
    const float* G = (dir == 0) ? out2 : out1;

    float kd[KNEG]; int ki[KNEG];
    #pragma unroll
    for (int k = 0; k < KNEG; ++k) { kd[k] = 3.0e38f; ki[k] = 0x7fffffff; }

    for (int seg = 0; seg < SSEG; ++seg) {
        const int cnt = g_cnt[dir][tt][seg];
        const int* pool = &g_pool[dir][tt][seg][0];
        for (int k = 0; k < cnt; ++k) {
            int idx = pool[k];
            idx = min(idx, NPTS - 1);
            const float* nr = G + idx * DIM;
            float dsum = 0.0f;
            #pragma unroll
            for (int j = 0; j < 4; ++j) dsum += fabsf(selfv[j] - nr[lane + 32 * j]);
            dsum = warp_sum(dsum);
            if (lane == 0) {
                bool better = (dsum < kd[KNEG - 1]) ||
                              (dsum == kd[KNEG - 1] && idx < ki[KNEG - 1]);
                if (better) {
                    int pos = KNEG - 1;
                    #pragma unroll
                    for (int q = KNEG - 2; q >= 0; --q)
                        if (kd[q] > dsum || (kd[q] == dsum && ki[q] > idx)) pos = q;
                    #pragma unroll
                    for (int q = KNEG - 1; q > 0; --q)
                        if (q > pos) { kd[q] = kd[q - 1]; ki[q] = ki[q - 1]; }
                    kd[pos] = dsum; ki[pos] = idx;
                }
            }
        }
    }
    if (lane == 0) {
        float lsum = 0.0f;
        #pragma unroll
        for (int k = 0; k < KNEG; ++k) lsum += fmaxf(Dm - kd[k], 0.0f);
        g_partial[g] = lsum;
    }
}

// ---------------- kernel 5: deterministic reduction ----------------
__global__ void reduce_kernel(float* __restrict__ out) {
    __shared__ float sh[1024];
    int t = threadIdx.x;
    sh[t] = g_partial[t] + g_partial[t + 1024];
    __syncthreads();
    #pragma unroll
    for (int s = 512; s > 0; s >>= 1) {
        if (t < s) sh[t] += sh[t + s];
        __syncthreads();
    }
    if (t == 0) out[0] = sh[0] * (1.0f / (float)(TANCH * KNEG));
}

// ---------------- launch ----------------
extern "C" void kernel_launch(void* const* d_in, const int* in_sizes, int n_in,
                              void* d_out, int out_size) {
    const float* out1 = (const float*)d_in[0];
    const float* out2 = (const float*)d_in[1];
    const int* anchor1 = (const int*)d_in[2];
    const int* anchor2 = (const int*)d_in[3];
    float* out = (float*)d_out;

    quant_transpose_kernel<<<dim3(N_PAD / 32, 1, 2), dim3(32, 8)>>>(out1, out2);

    tau_kernel<<<2 * TANCH / 8, 256>>>(out1, out2, anchor1, anchor2);

    mine_kernel<<<dim3(TANCH / MA, SSEG, 2), 256>>>(out1, out2, anchor1, anchor2);

    refine_loss_kernel<<<2 * TANCH / 8, 256>>>(out1, out2, anchor1, anchor2);

    reduce_kernel<<<1, 1024>>>(out);
}

// round 7
// speedup vs baseline: 2.8420x; 1.2608x over previous
#include <cuda_runtime.h>
#include <cstdint>

#define NPTS 50000
#define DIM  128
#define W4   (DIM / 4)
#define TANCH 1024
#define KNEG 10
#define GAMMA 1.0f
#define QSCALE 20.0f

#define MA 32                 // anchors per CTA (4 per warp)
#define TN 256                // candidates per tile
#define CW 8                  // words per chunk (32 dims)
#define NCH (W4 / CW)         // 4
#define STAGES 3
#define SSEG 4
#define TILES_PER_SEG 50
#define SEG_LEN (TILES_PER_SEG * TN)    // 12800
#define N_PAD (SSEG * SEG_LEN)          // 51200
#define TOTCH (TILES_PER_SEG * NCH)     // 200

#define NSAMP 2048            // tau sample size
#define KTAU 24               // tau = 24th smallest sample key -> pool ~585
#define PCAP 320              // pool capacity per (anchor, segment)

// ---------------- static scratch ----------------
__device__ uint32_t g_BTq[2][W4][N_PAD];    // packed s8x4, transposed; pad word = 0
__device__ uint32_t g_Qrow[2][NPTS][W4];    // packed s8x4, row-major (for tau sampling)
__device__ int g_sumb2[2][N_PAD];           // per-point sum of squares (pad = huge)
__device__ int g_tau[2][TANCH];
__device__ int g_pool[2][TANCH][SSEG][PCAP];
__device__ int g_cnt[2][TANCH][SSEG];
__device__ float g_partial[2 * TANCH];

// ---------------- helpers ----------------
__device__ __forceinline__ int dp4a(int acc, uint32_t a, uint32_t b) {
    int r;
    asm("dp4a.s32.s32 %0, %1, %2, %3;" : "=r"(r) : "r"(a), "r"(b), "r"(acc));
    return r;
}
__device__ __forceinline__ int quants(float v) {
    return min(127, max(-127, __float2int_rn(v * QSCALE)));
}
__device__ __forceinline__ uint32_t pack4(int q0, int q1, int q2, int q3) {
    return (uint32_t)(q0 & 0xFF) | ((uint32_t)(q1 & 0xFF) << 8) |
           ((uint32_t)(q2 & 0xFF) << 16) | ((uint32_t)(q3 & 0xFF) << 24);
}
__device__ __forceinline__ void cp_async16(uint32_t s, const void* g) {
    asm volatile("cp.async.cg.shared.global [%0], [%1], 16;\n" :: "r"(s), "l"(g));
}
__device__ __forceinline__ void cp_commit() { asm volatile("cp.async.commit_group;\n"); }
template <int N> __device__ __forceinline__ void cp_wait() {
    asm volatile("cp.async.wait_group %0;\n" :: "n"(N));
}
__device__ __forceinline__ float warp_sum(float v) {
    #pragma unroll
    for (int o = 16; o > 0; o >>= 1) v += __shfl_xor_sync(0xffffffffu, v, o);
    return v;
}
__device__ __forceinline__ int warp_min(int v) {
    #pragma unroll
    for (int o = 16; o > 0; o >>= 1) v = min(v, __shfl_xor_sync(0xffffffffu, v, o));
    return v;
}

// ---------------- kernel 1: quantize + pack + transpose + row copy + sumsq ----------------
__global__ void quant_transpose_kernel(const float* __restrict__ out1,
                                       const float* __restrict__ out2) {
    __shared__ uint32_t tile[32][33];
    const float* src = (blockIdx.z == 0) ? out1 : out2;
    uint32_t* dstT = &g_BTq[blockIdx.z][0][0];
    uint32_t* dstR = &g_Qrow[blockIdx.z][0][0];
    const int nBase = blockIdx.x * 32;
    const int tx = threadIdx.x, ty = threadIdx.y;
    #pragma unroll
    for (int j = 0; j < 32; j += 8) {
        int n = nBase + ty + j;
        uint32_t w = 0;
        int sq = 0x01000000;                 // pad: total = 0x20000000
        if (n < NPTS) {
            float4 v = *(const float4*)(src + n * DIM + 4 * tx);
            int q0 = quants(v.x), q1 = quants(v.y), q2 = quants(v.z), q3 = quants(v.w);
            w = pack4(q0, q1, q2, q3);
            sq = q0 * q0 + q1 * q1 + q2 * q2 + q3 * q3;
            dstR[n * W4 + tx] = w;
        }
        tile[ty + j][tx] = w;
        int tot = sq;
        #pragma unroll
        for (int o = 16; o > 0; o >>= 1) tot += __shfl_xor_sync(0xffffffffu, tot, o);
        if (tx == 0) g_sumb2[blockIdx.z][n] = tot;
    }
    __syncthreads();
    #pragma unroll
    for (int j = 0; j < 32; j += 8) {
        int d4 = ty + j;
        dstT[d4 * N_PAD + nBase + tx] = tile[tx][d4];
    }
}

// ---------------- kernel 2: tau threshold (24th smallest sample key) ----------------
__global__ __launch_bounds__(256)
void tau_kernel(const float* __restrict__ out1, const float* __restrict__ out2,
                const int* __restrict__ anchor1, const int* __restrict__ anchor2) {
    __shared__ uint32_t A_s[8][W4];
    const int warpId = threadIdx.x >> 5;
    const int lane = threadIdx.x & 31;
    const int g = blockIdx.x * 8 + warpId;
    const int dir = g >> 10;
    const int tt = g & 1023;
    const int bsel = (dir == 0) ? 1 : 0;
    const float* Arows = (dir == 0) ? out1 : out2;
    const int* anch = (dir == 0) ? anchor1 : anchor2;

    {
        float4 v = *(const float4*)(Arows + anch[tt] * DIM + 4 * lane);
        A_s[warpId][lane] = pack4(quants(v.x), quants(v.y), quants(v.z), quants(v.w));
    }
    __syncwarp();

    int kd[KTAU];
    #pragma unroll
    for (int k = 0; k < KTAU; ++k) kd[k] = 0x7fffffff;

    const uint32_t* A = A_s[warpId];
    for (int i = 0; i < NSAMP / 32; ++i) {
        int n = i * 32 + lane;
        const uint4* rp = (const uint4*)&g_Qrow[bsel][n][0];
        int dot = 0;
        #pragma unroll
        for (int w8 = 0; w8 < 8; ++w8) {
            uint4 b = rp[w8];
            uint4 a = *(const uint4*)&A[w8 * 4];
            dot = dp4a(dot, a.x, b.x);
            dot = dp4a(dot, a.y, b.y);
            dot = dp4a(dot, a.z, b.z);
            dot = dp4a(dot, a.w, b.w);
        }
        int key = g_sumb2[bsel][n] - 2 * dot;
        if (key < kd[KTAU - 1]) {
            #pragma unroll
            for (int j = KTAU - 1; j > 0; --j)
                kd[j] = min(kd[j], max(kd[j - 1], key));
            kd[0] = min(kd[0], key);
        }
    }

    // extract 24th smallest across warp
    int tauv = 0x7fffffff;
    #pragma unroll
    for (int r = 0; r < KTAU; ++r) {
        int gm = warp_min(kd[0]);
        if (kd[0] == gm) {
            #pragma unroll
            for (int j = 0; j < KTAU - 1; ++j) kd[j] = kd[j + 1];
            kd[KTAU - 1] = 0x7fffffff;
        }
        tauv = gm;
    }
    if (lane == 0) g_tau[dir][tt] = tauv;
}

// ---------------- kernel 3: dp4a mining (conflict-free smem), pool append ----------------
__global__ __launch_bounds__(256, 3)
void mine_kernel(const float* __restrict__ out1, const float* __restrict__ out2,
                 const int* __restrict__ anchor1, const int* __restrict__ anchor2) {
    __shared__ uint32_t Aq[W4][MA];            // 4 KB
    __shared__ uint32_t Bq[STAGES][CW][TN];    // 24 KB
    __shared__ int tau_s[MA];

    const int dir = blockIdx.z;
    const int bsel = (dir == 0) ? 1 : 0;
    const int tBase = blockIdx.x * MA;
    const int seg = blockIdx.y;
    const float* Arows = (dir == 0) ? out1 : out2;
    const int*   anch  = (dir == 0) ? anchor1 : anchor2;
    const uint32_t* BTq = &g_BTq[bsel][0][0];

    const int t = threadIdx.x;
    const int lane = t & 31;
    const int warpId = t >> 5;
    const int aB = warpId * 4;
    const int cL = lane * 4;             // low candidate group base (words)
    const int segStart = seg * SEG_LEN;

    // quantize 32 anchor rows into Aq[word][anchor]
    #pragma unroll
    for (int i = 0; i < 4; ++i) {
        int id = t + 256 * i;          // id = a*32 + w
        int a = id >> 5, w = id & 31;
        float4 v = *(const float4*)(Arows + anch[tBase + a] * DIM + 4 * w);
        Aq[w][a] = pack4(quants(v.x), quants(v.y), quants(v.z), quants(v.w));
    }
    if (t < MA) tau_s[t] = g_tau[dir][tBase + t];
    __syncthreads();

    int taus[4];
    #pragma unroll
    for (int a = 0; a < 4; ++a) taus[a] = tau_s[aB + a];
    int cnt[4] = {0, 0, 0, 0};

    auto load_chunk = [&](int s, int g) {
        uint32_t sb = (uint32_t)__cvta_generic_to_shared(&Bq[s][0][0]);
        const int n0 = segStart + (g >> 2) * TN;
        const int rowBase = (g & 3) * CW;
        #pragma unroll
        for (int i = 0; i < 2; ++i) {
            int id = t + 256 * i;              // 512 x 16B
            int r = id >> 6;
            int c4 = (id & 63) * 4;
            const uint32_t* gp = BTq + (rowBase + r) * N_PAD + n0 + c4;
            cp_async16(sb + (uint32_t)((r * TN + c4) * 4), gp);
        }
        cp_commit();
    };

    load_chunk(0, 0);
    load_chunk(1, 1);

    for (int tile = 0; tile < TILES_PER_SEG; ++tile) {
        int acc[4][8];
        #pragma unroll
        for (int a = 0; a < 4; ++a)
            #pragma unroll
            for (int j = 0; j < 8; ++j) acc[a][j] = 0;

        #pragma unroll
        for (int c = 0; c < NCH; ++c) {
            const int g = tile * NCH + c;
            if (g + 1 < TOTCH) cp_wait<1>(); else cp_wait<0>();
            __syncthreads();
            if (g + 2 < TOTCH) load_chunk((g + 2) % STAGES, g + 2);

            const uint32_t* B = &Bq[g % STAGES][0][0];
            #pragma unroll
            for (int w = 0; w < CW; ++w) {
                uint4 av = *(const uint4*)&Aq[c * CW + w][aB];
                uint4 b0 = *(const uint4*)&B[w * TN + cL];           // words lane*4..+3
                uint4 b1 = *(const uint4*)&B[w * TN + 128 + cL];     // words 128+lane*4..+3
                const uint32_t avr[4] = {av.x, av.y, av.z, av.w};
                const uint32_t bw[8] = {b0.x, b0.y, b0.z, b0.w, b1.x, b1.y, b1.z, b1.w};
                #pragma unroll
                for (int a = 0; a < 4; ++a)
                    #pragma unroll
                    for (int j = 0; j < 8; ++j)
                        acc[a][j] = dp4a(acc[a][j], avr[a], bw[j]);
            }
        }

        // finalize keys + threshold append
        const int n0 = segStart + tile * TN;
        int4 sa = *(const int4*)&g_sumb2[bsel][n0 + cL];
        int4 sb = *(const int4*)&g_sumb2[bsel][n0 + 128 + cL];
        const int s2[8] = {sa.x, sa.y, sa.z, sa.w, sb.x, sb.y, sb.z, sb.w};
        #pragma unroll
        for (int a = 0; a < 4; ++a) {
            #pragma unroll
            for (int j = 0; j < 8; ++j) {
                int key = s2[j] - 2 * acc[a][j];
                unsigned m = __ballot_sync(0xffffffffu, key < taus[a]);
                const int jo = (j < 4) ? j : (128 + j - 4);
                while (m) {
                    int src = __ffs(m) - 1; m &= m - 1;
                    if (cnt[a] < PCAP && lane == 0)
                        g_pool[dir][tBase + aB + a][seg][cnt[a]] = n0 + src * 4 + jo;
                    cnt[a]++;
                }
            }
        }
    }

    if (lane == 0) {
        #pragma unroll
        for (int a = 0; a < 4; ++a)
            g_cnt[dir][tBase + aB + a][seg] = min(cnt[a], PCAP);
    }
}

// ---------------- kernel 4: candidate-parallel exact fp32 L1 re-rank + loss ----------------
__global__ __launch_bounds__(256)
void refine_loss_kernel(const float* __restrict__ out1, const float* __restrict__ out2,
                        const int* __restrict__ anchor1, const int* __restrict__ anchor2) {
    __shared__ float s_anc[8][DIM];
    const int warpId = threadIdx.x >> 5;
    const int lane = threadIdx.x & 31;
    const int g = blockIdx.x * 8 + warpId;
    const int dir = g >> 10;
    const int tt = g & 1023;

    const float* r1 = out1 + anchor1[tt] * DIM;
    const float* r2 = out2 + anchor2[tt] * DIM;
    float v1[4], v2[4];
    #pragma unroll
    for (int j = 0; j < 4; ++j) {
        v1[j] = r1[lane + 32 * j];
        v2[j] = r2[lane + 32 * j];
    }
    float A = 0.0f;
    #pragma unroll
    for (int j = 0; j < 4; ++j) A += fabsf(v1[j] - v2[j]);
    A = warp_sum(A);
    const float Dm = A + GAMMA;

    // stage self anchor row into smem (broadcast-readable)
    #pragma unroll
    for (int j = 0; j < 4; ++j)
        s_anc[warpId][lane + 32 * j] = (dir == 0) ? v1[j] : v2[j];
    __syncwarp();

    const float* G = (dir == 0) ? out2 : out1;
    const float4* anc4 = (const float4*)&s_anc[warpId][0];

    float kd[KNEG]; int ki[KNEG];
    #pragma unroll
    for (int k = 0; k < KNEG; ++k) { kd[k] = 3.0e38f; ki[k] = 0x7fffffff; }

    for (int seg = 0; seg < SSEG; ++seg) {
        const int cnt = g_cnt[dir][tt][seg];
        const int* pool = &g_pool[dir][tt][seg][0];
        for (int base = 0; base < cnt; base += 32) {
            const int k = base + lane;
            int idx = -1;
            float dsum = 3.0e38f;
            if (k < cnt) {
                idx = min(pool[k], NPTS - 1);
                const float4* nr = (const float4*)(G + idx * DIM);
                dsum = 0.0f;
                #pragma unroll 8
                for (int j = 0; j < 32; ++j) {
                    float4 b = nr[j];
                    float4 a = anc4[j];
                    dsum += fabsf(a.x - b.x) + fabsf(a.y - b.y) +
                            fabsf(a.z - b.z) + fabsf(a.w - b.w);
                }
            }
            float thr = __shfl_sync(0xffffffffu, kd[KNEG - 1], 0);
            int   thi = __shfl_sync(0xffffffffu, ki[KNEG - 1], 0);
            bool candp = (idx >= 0) && (dsum < thr || (dsum == thr && idx < thi));
            unsigned m = __ballot_sync(0xffffffffu, candp);
            while (m) {
                int src = __ffs(m) - 1; m &= m - 1;
                float d = __shfl_sync(0xffffffffu, dsum, src);
                int  ix = __shfl_sync(0xffffffffu, idx, src);
                if (lane == 0) {
                    bool better = (d < kd[KNEG - 1]) ||
                                  (d == kd[KNEG - 1] && ix < ki[KNEG - 1]);
                    if (better) {
                        int pos = KNEG - 1;
                        #pragma unroll
                        for (int q = KNEG - 2; q >= 0; --q)
                            if (kd[q] > d || (kd[q] == d && ki[q] > ix)) pos = q;
                        #pragma unroll
                        for (int q = KNEG - 1; q > 0; --q)
                            if (q > pos) { kd[q] = kd[q - 1]; ki[q] = ki[q - 1]; }
                        kd[pos] = d; ki[pos] = ix;
                    }
                }
            }
        }
    }
    if (lane == 0) {
        float lsum = 0.0f;
        #pragma unroll
        for (int k = 0; k < KNEG; ++k) lsum += fmaxf(Dm - kd[k], 0.0f);
        g_partial[g] = lsum;
    }
}

// ---------------- kernel 5: deterministic reduction ----------------
__global__ void reduce_kernel(float* __restrict__ out) {
    __shared__ float sh[1024];
    int t = threadIdx.x;
    sh[t] = g_partial[t] + g_partial[t + 1024];
    __syncthreads();
    #pragma unroll
    for (int s = 512; s > 0; s >>= 1) {
        if (t < s) sh[t] += sh[t + s];
        __syncthreads();
    }
    if (t == 0) out[0] = sh[0] * (1.0f / (float)(TANCH * KNEG));
}

// ---------------- launch ----------------
extern "C" void kernel_launch(void* const* d_in, const int* in_sizes, int n_in,
                              void* d_out, int out_size) {
    const float* out1 = (const float*)d_in[0];
    const float* out2 = (const float*)d_in[1];
    const int* anchor1 = (const int*)d_in[2];
    const int* anchor2 = (const int*)d_in[3];
    float* out = (float*)d_out;

    quant_transpose_kernel<<<dim3(N_PAD / 32, 1, 2), dim3(32, 8)>>>(out1, out2);

    tau_kernel<<<2 * TANCH / 8, 256>>>(out1, out2, anchor1, anchor2);

    mine_kernel<<<dim3(TANCH / MA, SSEG, 2), 256>>>(out1, out2, anchor1, anchor2);

    refine_loss_kernel<<<2 * TANCH / 8, 256>>>(out1, out2, anchor1, anchor2);

    reduce_kernel<<<1, 1024>>>(out);
}